// round 1
// baseline (speedup 1.0000x reference)
#include <cuda_runtime.h>

#define NB 4096
#define XS 132   // padded row stride for 64x128 fp32 tiles
#define SS 68    // padded row stride for 64x64 score tiles

// ---------- packed fp32x2 helpers (sm_100+/sm_103a FFMA2 path) ----------
static __device__ __forceinline__ unsigned long long pack2(float x){
    unsigned long long r;
    asm("mov.b64 %0, {%1, %1};" : "=l"(r) : "f"(x));
    return r;
}
static __device__ __forceinline__ void fma2(unsigned long long& d, unsigned long long a, unsigned long long b){
    asm("fma.rn.f32x2 %0, %1, %2, %0;" : "+l"(d) : "l"(a), "l"(b));
}
static __device__ __forceinline__ float2 unpack2(unsigned long long v){
    float2 r;
    asm("mov.b64 {%0, %1}, %2;" : "=f"(r.x), "=f"(r.y) : "l"(v));
    return r;
}

// ---------- generic 64xK @ Kx128 matmul into smem ----------
// MODE: 0 = plain store, 1 = relu(v+bias), 2 = relu(v+bias)*rowScale[row],
//       3 = accumulate into Y (no bias), 4 = store v+bias (no relu)
template<int K, int MODE>
static __device__ __forceinline__ void mm(
    const float* __restrict__ Xp, int xstr,
    const float* __restrict__ Wp, int wstr,
    const float* __restrict__ bias,
    const float* __restrict__ rowScale,
    float* __restrict__ Yp, int ystr)
{
    const int wid  = threadIdx.x >> 5;
    const int lane = threadIdx.x & 31;
    const int r0 = wid << 3;   // 8 rows per warp
    const int c  = lane << 2;  // 4 cols per lane
    unsigned long long acc[8][2];
#pragma unroll
    for (int r = 0; r < 8; ++r){ acc[r][0] = 0ull; acc[r][1] = 0ull; }
#pragma unroll 4
    for (int k = 0; k < K; k += 2){
        ulonglong2 w0 = *(const ulonglong2*)(Wp + (k    )*wstr + c);
        ulonglong2 w1 = *(const ulonglong2*)(Wp + (k + 1)*wstr + c);
#pragma unroll
        for (int r = 0; r < 8; ++r){
            float2 xv = *(const float2*)(Xp + (r0 + r)*xstr + k);
            unsigned long long x0 = pack2(xv.x);
            unsigned long long x1 = pack2(xv.y);
            fma2(acc[r][0], w0.x, x0);
            fma2(acc[r][1], w0.y, x0);
            fma2(acc[r][0], w1.x, x1);
            fma2(acc[r][1], w1.y, x1);
        }
    }
    float4 bb = make_float4(0.f, 0.f, 0.f, 0.f);
    if (MODE == 1 || MODE == 2 || MODE == 4) bb = *(const float4*)(bias + c);
#pragma unroll
    for (int r = 0; r < 8; ++r){
        float2 p0 = unpack2(acc[r][0]);
        float2 p1 = unpack2(acc[r][1]);
        float vx = p0.x + bb.x, vy = p0.y + bb.y, vz = p1.x + bb.z, vw = p1.y + bb.w;
        if (MODE == 1 || MODE == 2){
            vx = fmaxf(vx, 0.f); vy = fmaxf(vy, 0.f);
            vz = fmaxf(vz, 0.f); vw = fmaxf(vw, 0.f);
        }
        if (MODE == 2){
            float sc = rowScale[r0 + r];
            vx *= sc; vy *= sc; vz *= sc; vw *= sc;
        }
        float* yrow = Yp + (r0 + r)*ystr + c;
        if (MODE == 3){
            float4 o = *(const float4*)yrow;
            vx += o.x; vy += o.y; vz += o.z; vw += o.w;
        }
        *(float4*)yrow = make_float4(vx, vy, vz, vw);
    }
}

// ---------- S[i][j] = dot(T[i,:], E[j,:]) over 128 (packed over k) ----------
static __device__ __forceinline__ void mm_s(
    const float* __restrict__ Tp, const float* __restrict__ Ep, float* __restrict__ Sp)
{
    const int wid  = threadIdx.x >> 5;
    const int lane = threadIdx.x & 31;
    const int r0 = wid << 3;
    const int j0 = lane, j1 = lane + 32;
    unsigned long long acc[8][2];
#pragma unroll
    for (int r = 0; r < 8; ++r){ acc[r][0] = 0ull; acc[r][1] = 0ull; }
#pragma unroll 2
    for (int k = 0; k < 128; k += 4){
        ulonglong2 e0 = *(const ulonglong2*)(Ep + j0*XS + k);
        ulonglong2 e1 = *(const ulonglong2*)(Ep + j1*XS + k);
#pragma unroll
        for (int r = 0; r < 8; ++r){
            ulonglong2 tv = *(const ulonglong2*)(Tp + (r0 + r)*XS + k);
            fma2(acc[r][0], tv.x, e0.x);
            fma2(acc[r][0], tv.y, e0.y);
            fma2(acc[r][1], tv.x, e1.x);
            fma2(acc[r][1], tv.y, e1.y);
        }
    }
#pragma unroll
    for (int r = 0; r < 8; ++r){
        float2 p0 = unpack2(acc[r][0]);
        float2 p1 = unpack2(acc[r][1]);
        Sp[(r0 + r)*SS + j0] = p0.x + p0.y;
        Sp[(r0 + r)*SS + j1] = p1.x + p1.y;
    }
}

// ---------- SimGNN attention pooling (mask all-ones -> denom 64) ----------
static __device__ __forceinline__ void pool(
    const float* __restrict__ Xs, const float* __restrict__ Wp, float* __restrict__ out,
    float* __restrict__ mvec, float* __restrict__ ctxv, float* __restrict__ scores)
{
    const int t = threadIdx.x;
    const int wid = t >> 5, lane = t & 31;
    if (t < 128){
        float s = 0.f;
#pragma unroll 8
        for (int i = 0; i < 64; ++i) s += Xs[i*XS + t];
        mvec[t] = s * (1.0f / 64.0f);
    }
    __syncthreads();
    if (t < 128){
        float s = 0.f;
#pragma unroll 8
        for (int d = 0; d < 128; ++d) s += mvec[d] * Wp[d*128 + t];
        ctxv[t] = tanhf(s);
    }
    __syncthreads();
#pragma unroll
    for (int r = 0; r < 8; ++r){
        int row = wid*8 + r;
        float4 x4 = *(const float4*)(Xs + row*XS + (lane << 2));
        float4 c4 = *(const float4*)(ctxv + (lane << 2));
        float s = x4.x*c4.x + x4.y*c4.y + x4.z*c4.z + x4.w*c4.w;
#pragma unroll
        for (int o = 16; o; o >>= 1) s += __shfl_xor_sync(0xffffffffu, s, o);
        if (lane == 0) scores[row] = 1.0f / (1.0f + __expf(-s));
    }
    __syncthreads();
    if (t < 128){
        float g = 0.f;
#pragma unroll 8
        for (int i = 0; i < 64; ++i) g += Xs[i*XS + t] * scores[i];
        out[t] = g;
    }
}

__global__ void __launch_bounds__(256, 1) CGFA_19533511262348_kernel(
    const float* __restrict__ A_src, const float* __restrict__ emb_src,
    const float* __restrict__ A_dst, const float* __restrict__ emb_dst,
    const float* __restrict__ Wa, const float* __restrict__ ba,
    const float* __restrict__ Wu, const float* __restrict__ bu,
    const float* __restrict__ Aff, const float* __restrict__ Wc, const float* __restrict__ bc,
    const float* __restrict__ Wp1, const float* __restrict__ Wp2,
    float* __restrict__ out)
{
    extern __shared__ float smf[];
    float* E1     = smf;                 // 64*132
    float* E2     = E1 + 64*XS;          // 64*132
    float* Tt     = E2 + 64*XS;          // 64*132 scratch
    float* Xs     = Tt + 64*XS;          // 64*132 scratch
    float* As     = Xs + 64*XS;          // 64*64
    float* Sm     = As + 64*64;          // 64*68
    float* S2     = Sm + 64*SS;          // 64*68
    float* colInv = S2 + 64*SS;          // 64
    float* rmax   = colInv + 64;
    float* rsumI  = rmax + 64;
    float* cmax   = rsumI + 64;
    float* csumI  = cmax + 64;
    float* mvec   = csumI + 64;          // 128
    float* ctxv   = mvec + 128;          // 128
    float* scores = ctxv + 128;          // 64

    const int b = blockIdx.x;
    const int t = threadIdx.x;

    // ===== Siamese intra-graph conv: emb = An @ relu(x@Wa+ba) + relu(x@Wu+bu) =====
    for (int g = 0; g < 2; ++g){
        const float* Ain = g ? A_dst : A_src;
        const float* Ein = g ? emb_dst : emb_src;
        float* Eout = g ? E2 : E1;
        for (int e = t*4; e < 64*128; e += 256*4){
            float4 v = *(const float4*)(Ein + (size_t)b*64*128 + e);
            *(float4*)(Xs + (e >> 7)*XS + (e & 127)) = v;
        }
        for (int e = t*4; e < 64*64; e += 256*4){
            *(float4*)(As + e) = *(const float4*)(Ain + (size_t)b*64*64 + e);
        }
        __syncthreads();
        if (t < 64){
            float s = 0.f;
#pragma unroll 8
            for (int i = 0; i < 64; ++i) s += As[i*64 + t];
            colInv[t] = 1.0f / fmaxf(s, 1e-12f);   // column-normalizer of A
        }
        __syncthreads();
        mm<128,1>(Xs, XS, Wu, 128, bu, nullptr, Eout, XS);   // Eout = relu(x@Wu+bu)
        mm<128,2>(Xs, XS, Wa, 128, ba, colInv, Tt, XS);      // T = relu(x@Wa+ba)/colsum[row]
        __syncthreads();
        mm<64,3>(As, 64, Tt, XS, nullptr, nullptr, Eout, XS);// Eout += A @ T  (== An @ ax)
        __syncthreads();
    }

    // ===== affinity: S = (E1 @ Aff) @ E2^T =====
    mm<128,0>(E1, XS, Aff, 128, nullptr, nullptr, Tt, XS);
    __syncthreads();
    mm_s(Tt, E2, Sm);
    __syncthreads();

    // ===== bidirectional softmax stats (masks all true) =====
    if (t < 64){
        float mx = -1e30f;
        for (int j = 0; j < 64; ++j) mx = fmaxf(mx, Sm[t*SS + j]);
        float s = 0.f;
        for (int j = 0; j < 64; ++j) s += __expf(Sm[t*SS + j] - mx);
        rmax[t] = mx; rsumI[t] = 1.0f / s;
    } else if (t < 128){
        int j = t - 64;
        float mx = -1e30f;
        for (int i = 0; i < 64; ++i) mx = fmaxf(mx, Sm[i*SS + j]);
        float s = 0.f;
        for (int i = 0; i < 64; ++i) s += __expf(Sm[i*SS + j] - mx);
        cmax[j] = mx; csumI[j] = 1.0f / s;
    }
    __syncthreads();
    for (int e = t; e < 4096; e += 256){
        int i = e >> 6, j = e & 63;
        float v = Sm[i*SS + j];
        S2[j*SS + i] = __expf(v - cmax[j]) * csumI[j];   // col-softmax, stored transposed
        Sm[i*SS + j] = __expf(v - rmax[i]) * rsumI[i];   // row-softmax, in place
    }
    __syncthreads();

    // ===== new1 = [E1, Sm@E2] @ Wc + bc ; pool -> g1 =====
    mm<64,0>(Sm, SS, E2, XS, nullptr, nullptr, Tt, XS);          // att1
    __syncthreads();
    mm<128,4>(E1, XS, Wc, 128, bc, nullptr, Xs, XS);             // E1 @ Wc[:128] + bc
    mm<128,3>(Tt, XS, Wc + 128*128, 128, nullptr, nullptr, Xs, XS); // += att1 @ Wc[128:]
    __syncthreads();
    pool(Xs, Wp1, out + (size_t)b*128, mvec, ctxv, scores);
    __syncthreads();

    // ===== new2 = [E2, S2@E1] @ Wc + bc ; pool -> g2 =====
    mm<64,0>(S2, SS, E1, XS, nullptr, nullptr, Tt, XS);          // att2
    __syncthreads();
    mm<128,4>(E2, XS, Wc, 128, bc, nullptr, Xs, XS);
    mm<128,3>(Tt, XS, Wc + 128*128, 128, nullptr, nullptr, Xs, XS);
    __syncthreads();
    pool(Xs, Wp2, out + (size_t)(NB + b)*128, mvec, ctxv, scores);
}

extern "C" void kernel_launch(void* const* d_in, const int* in_sizes, int n_in,
                              void* d_out, int out_size)
{
    (void)in_sizes; (void)n_in; (void)out_size;
    const float* A_src   = (const float*)d_in[0];
    const float* emb_src = (const float*)d_in[1];
    // d_in[2] = mask_src (all ones, unused)
    const float* A_dst   = (const float*)d_in[3];
    const float* emb_dst = (const float*)d_in[4];
    // d_in[5] = mask_dst (all ones, unused)
    const float* Wa  = (const float*)d_in[6];
    const float* ba  = (const float*)d_in[7];
    const float* Wu  = (const float*)d_in[8];
    const float* bu  = (const float*)d_in[9];
    const float* Aff = (const float*)d_in[10];
    const float* Wc  = (const float*)d_in[11];
    const float* bc  = (const float*)d_in[12];
    const float* Wp1 = (const float*)d_in[13];
    const float* Wp2 = (const float*)d_in[14];
    float* out = (float*)d_out;

    const int smem_bytes = (64*XS*4 + 64*64 + 64*SS*2 + 64*5 + 128*2 + 64) * (int)sizeof(float);
    cudaFuncSetAttribute(CGFA_19533511262348_kernel,
                         cudaFuncAttributeMaxDynamicSharedMemorySize, smem_bytes);
    CGFA_19533511262348_kernel<<<NB, 256, smem_bytes>>>(
        A_src, emb_src, A_dst, emb_dst,
        Wa, ba, Wu, bu, Aff, Wc, bc, Wp1, Wp2, out);
}

// round 2
// speedup vs baseline: 1.0437x; 1.0437x over previous
#include <cuda_runtime.h>

#define NB 4096
#define XS 132   // padded row stride for 64x128 fp32 tiles
#define SS 68    // padded row stride for 64x64 score tiles

// ---------- packed fp32x2 helpers (sm_100+/sm_103a FFMA2 path) ----------
static __device__ __forceinline__ unsigned long long pack2(float x){
    unsigned long long r;
    asm("mov.b64 %0, {%1, %1};" : "=l"(r) : "f"(x));
    return r;
}
static __device__ __forceinline__ void fma2(unsigned long long& d, unsigned long long a, unsigned long long b){
    asm("fma.rn.f32x2 %0, %1, %2, %0;" : "+l"(d) : "l"(a), "l"(b));
}
static __device__ __forceinline__ float2 unpack2(unsigned long long v){
    float2 r;
    asm("mov.b64 {%0, %1}, %2;" : "=f"(r.x), "=f"(r.y) : "l"(v));
    return r;
}

// ---------- generic 64xK @ Kx128 matmul into smem ----------
// MODE: 0 = plain store, 1 = relu(v+bias), 2 = relu(v+bias)*rowScale[row],
//       3 = accumulate into Y (no bias), 4 = store v+bias (no relu)
template<int K, int MODE>
static __device__ __forceinline__ void mm(
    const float* __restrict__ Xp, int xstr,
    const float* __restrict__ Wp, int wstr,
    const float* __restrict__ bias,
    const float* __restrict__ rowScale,
    float* __restrict__ Yp, int ystr)
{
    const int wid  = threadIdx.x >> 5;
    const int lane = threadIdx.x & 31;
    const int r0 = wid << 3;   // 8 rows per warp
    const int c  = lane << 2;  // 4 cols per lane
    unsigned long long acc[8][2];
#pragma unroll
    for (int r = 0; r < 8; ++r){ acc[r][0] = 0ull; acc[r][1] = 0ull; }
#pragma unroll 4
    for (int k = 0; k < K; k += 2){
        ulonglong2 w0 = *(const ulonglong2*)(Wp + (k    )*wstr + c);
        ulonglong2 w1 = *(const ulonglong2*)(Wp + (k + 1)*wstr + c);
#pragma unroll
        for (int r = 0; r < 8; ++r){
            float2 xv = *(const float2*)(Xp + (r0 + r)*xstr + k);
            unsigned long long x0 = pack2(xv.x);
            unsigned long long x1 = pack2(xv.y);
            fma2(acc[r][0], w0.x, x0);
            fma2(acc[r][1], w0.y, x0);
            fma2(acc[r][0], w1.x, x1);
            fma2(acc[r][1], w1.y, x1);
        }
    }
    float4 bb = make_float4(0.f, 0.f, 0.f, 0.f);
    if (MODE == 1 || MODE == 2 || MODE == 4) bb = *(const float4*)(bias + c);
#pragma unroll
    for (int r = 0; r < 8; ++r){
        float2 p0 = unpack2(acc[r][0]);
        float2 p1 = unpack2(acc[r][1]);
        float vx = p0.x + bb.x, vy = p0.y + bb.y, vz = p1.x + bb.z, vw = p1.y + bb.w;
        if (MODE == 1 || MODE == 2){
            vx = fmaxf(vx, 0.f); vy = fmaxf(vy, 0.f);
            vz = fmaxf(vz, 0.f); vw = fmaxf(vw, 0.f);
        }
        if (MODE == 2){
            float sc = rowScale[r0 + r];
            vx *= sc; vy *= sc; vz *= sc; vw *= sc;
        }
        float* yrow = Yp + (r0 + r)*ystr + c;
        if (MODE == 3){
            float4 o = *(const float4*)yrow;
            vx += o.x; vy += o.y; vz += o.z; vw += o.w;
        }
        *(float4*)yrow = make_float4(vx, vy, vz, vw);
    }
}

// ---------- S[i][j] = dot(T[i,:], E[j,:]) over 128 (packed over k) ----------
static __device__ __forceinline__ void mm_s(
    const float* __restrict__ Tp, const float* __restrict__ Ep, float* __restrict__ Sp)
{
    const int wid  = threadIdx.x >> 5;
    const int lane = threadIdx.x & 31;
    const int r0 = wid << 3;
    const int j0 = lane, j1 = lane + 32;
    unsigned long long acc[8][2];
#pragma unroll
    for (int r = 0; r < 8; ++r){ acc[r][0] = 0ull; acc[r][1] = 0ull; }
#pragma unroll 2
    for (int k = 0; k < 128; k += 4){
        ulonglong2 e0 = *(const ulonglong2*)(Ep + j0*XS + k);
        ulonglong2 e1 = *(const ulonglong2*)(Ep + j1*XS + k);
#pragma unroll
        for (int r = 0; r < 8; ++r){
            ulonglong2 tv = *(const ulonglong2*)(Tp + (r0 + r)*XS + k);
            fma2(acc[r][0], tv.x, e0.x);
            fma2(acc[r][0], tv.y, e0.y);
            fma2(acc[r][1], tv.x, e1.x);
            fma2(acc[r][1], tv.y, e1.y);
        }
    }
#pragma unroll
    for (int r = 0; r < 8; ++r){
        float2 p0 = unpack2(acc[r][0]);
        float2 p1 = unpack2(acc[r][1]);
        Sp[(r0 + r)*SS + j0] = p0.x + p0.y;
        Sp[(r0 + r)*SS + j1] = p1.x + p1.y;
    }
}

// ---------- SimGNN attention pooling (mask all-ones -> denom 64) ----------
static __device__ __forceinline__ void pool(
    const float* __restrict__ Xs, const float* __restrict__ Wp, float* __restrict__ out,
    float* __restrict__ mvec, float* __restrict__ ctxv, float* __restrict__ scores)
{
    const int t = threadIdx.x;
    const int wid = t >> 5, lane = t & 31;
    if (t < 128){
        float s = 0.f;
#pragma unroll 8
        for (int i = 0; i < 64; ++i) s += Xs[i*XS + t];
        mvec[t] = s * (1.0f / 64.0f);
    }
    __syncthreads();
    if (t < 128){
        float s = 0.f;
#pragma unroll 8
        for (int d = 0; d < 128; ++d) s += mvec[d] * Wp[d*128 + t];
        ctxv[t] = tanhf(s);
    }
    __syncthreads();
#pragma unroll
    for (int r = 0; r < 8; ++r){
        int row = wid*8 + r;
        float4 x4 = *(const float4*)(Xs + row*XS + (lane << 2));
        float4 c4 = *(const float4*)(ctxv + (lane << 2));
        float s = x4.x*c4.x + x4.y*c4.y + x4.z*c4.z + x4.w*c4.w;
#pragma unroll
        for (int o = 16; o; o >>= 1) s += __shfl_xor_sync(0xffffffffu, s, o);
        if (lane == 0) scores[row] = 1.0f / (1.0f + __expf(-s));
    }
    __syncthreads();
    if (t < 128){
        float g = 0.f;
#pragma unroll 8
        for (int i = 0; i < 64; ++i) g += Xs[i*XS + t] * scores[i];
        out[t] = g;
    }
}

__global__ void __launch_bounds__(256, 1) CGFA_19533511262348_kernel(
    const float* __restrict__ A_src, const float* __restrict__ emb_src,
    const float* __restrict__ A_dst, const float* __restrict__ emb_dst,
    const float* __restrict__ Wa, const float* __restrict__ ba,
    const float* __restrict__ Wu, const float* __restrict__ bu,
    const float* __restrict__ Aff, const float* __restrict__ Wc, const float* __restrict__ bc,
    const float* __restrict__ Wp1, const float* __restrict__ Wp2,
    float* __restrict__ out)
{
    extern __shared__ float smf[];
    float* E1     = smf;                 // 64*132
    float* E2     = E1 + 64*XS;          // 64*132
    float* Tt     = E2 + 64*XS;          // 64*132 scratch
    float* Xs     = Tt + 64*XS;          // 64*132 scratch
    float* As     = Xs + 64*XS;          // 64*64
    float* Sm     = As + 64*64;          // 64*68
    float* S2     = Sm + 64*SS;          // 64*68
    float* colInv = S2 + 64*SS;          // 64
    float* rmax   = colInv + 64;
    float* rsumI  = rmax + 64;
    float* cmax   = rsumI + 64;
    float* csumI  = cmax + 64;
    float* mvec   = csumI + 64;          // 128
    float* ctxv   = mvec + 128;          // 128
    float* scores = ctxv + 128;          // 64

    const int b = blockIdx.x;
    const int t = threadIdx.x;

    // ===== Siamese intra-graph conv: emb = An @ relu(x@Wa+ba) + relu(x@Wu+bu) =====
    for (int g = 0; g < 2; ++g){
        const float* Ain = g ? A_dst : A_src;
        const float* Ein = g ? emb_dst : emb_src;
        float* Eout = g ? E2 : E1;
        for (int e = t*4; e < 64*128; e += 256*4){
            float4 v = *(const float4*)(Ein + (size_t)b*64*128 + e);
            *(float4*)(Xs + (e >> 7)*XS + (e & 127)) = v;
        }
        for (int e = t*4; e < 64*64; e += 256*4){
            *(float4*)(As + e) = *(const float4*)(Ain + (size_t)b*64*64 + e);
        }
        __syncthreads();
        if (t < 64){
            float s = 0.f;
#pragma unroll 8
            for (int i = 0; i < 64; ++i) s += As[i*64 + t];
            colInv[t] = 1.0f / fmaxf(s, 1e-12f);   // column-normalizer of A
        }
        __syncthreads();
        mm<128,1>(Xs, XS, Wu, 128, bu, nullptr, Eout, XS);   // Eout = relu(x@Wu+bu)
        mm<128,2>(Xs, XS, Wa, 128, ba, colInv, Tt, XS);      // T = relu(x@Wa+ba)/colsum[row]
        __syncthreads();
        mm<64,3>(As, 64, Tt, XS, nullptr, nullptr, Eout, XS);// Eout += A @ T  (== An @ ax)
        __syncthreads();
    }

    // ===== affinity: S = (E1 @ Aff) @ E2^T =====
    mm<128,0>(E1, XS, Aff, 128, nullptr, nullptr, Tt, XS);
    __syncthreads();
    mm_s(Tt, E2, Sm);
    __syncthreads();

    // ===== bidirectional softmax stats (masks all true) =====
    if (t < 64){
        float mx = -1e30f;
        for (int j = 0; j < 64; ++j) mx = fmaxf(mx, Sm[t*SS + j]);
        float s = 0.f;
        for (int j = 0; j < 64; ++j) s += __expf(Sm[t*SS + j] - mx);
        rmax[t] = mx; rsumI[t] = 1.0f / s;
    } else if (t < 128){
        int j = t - 64;
        float mx = -1e30f;
        for (int i = 0; i < 64; ++i) mx = fmaxf(mx, Sm[i*SS + j]);
        float s = 0.f;
        for (int i = 0; i < 64; ++i) s += __expf(Sm[i*SS + j] - mx);
        cmax[j] = mx; csumI[j] = 1.0f / s;
    }
    __syncthreads();
    for (int e = t; e < 4096; e += 256){
        int i = e >> 6, j = e & 63;
        float v = Sm[i*SS + j];
        S2[j*SS + i] = __expf(v - cmax[j]) * csumI[j];   // col-softmax, stored transposed
        Sm[i*SS + j] = __expf(v - rmax[i]) * rsumI[i];   // row-softmax, in place
    }
    __syncthreads();

    // ===== new1 = [E1, Sm@E2] @ Wc + bc ; pool -> g1 =====
    mm<64,0>(Sm, SS, E2, XS, nullptr, nullptr, Tt, XS);          // att1
    __syncthreads();
    mm<128,4>(E1, XS, Wc, 128, bc, nullptr, Xs, XS);             // E1 @ Wc[:128] + bc
    mm<128,3>(Tt, XS, Wc + 128*128, 128, nullptr, nullptr, Xs, XS); // += att1 @ Wc[128:]
    __syncthreads();
    pool(Xs, Wp1, out + (size_t)b*128, mvec, ctxv, scores);
    __syncthreads();

    // ===== new2 = [E2, S2@E1] @ Wc + bc ; pool -> g2 =====
    mm<64,0>(S2, SS, E1, XS, nullptr, nullptr, Tt, XS);          // att2
    __syncthreads();
    mm<128,4>(E2, XS, Wc, 128, bc, nullptr, Xs, XS);
    mm<128,3>(Tt, XS, Wc + 128*128, 128, nullptr, nullptr, Xs, XS);
    __syncthreads();
    pool(Xs, Wp2, out + (size_t)(NB + b)*128, mvec, ctxv, scores);
}

extern "C" void kernel_launch(void* const* d_in, const int* in_sizes, int n_in,
                              void* d_out, int out_size)
{
    (void)in_sizes; (void)n_in; (void)out_size;
    const float* A_src   = (const float*)d_in[0];
    const float* emb_src = (const float*)d_in[1];
    // d_in[2] = mask_src (all ones, unused)
    const float* A_dst   = (const float*)d_in[3];
    const float* emb_dst = (const float*)d_in[4];
    // d_in[5] = mask_dst (all ones, unused)
    const float* Wa  = (const float*)d_in[6];
    const float* ba  = (const float*)d_in[7];
    const float* Wu  = (const float*)d_in[8];
    const float* bu  = (const float*)d_in[9];
    const float* Aff = (const float*)d_in[10];
    const float* Wc  = (const float*)d_in[11];
    const float* bc  = (const float*)d_in[12];
    const float* Wp1 = (const float*)d_in[13];
    const float* Wp2 = (const float*)d_in[14];
    float* out = (float*)d_out;

    const int smem_bytes = (64*XS*4 + 64*64 + 64*SS*2 + 64*5 + 128*2 + 64) * (int)sizeof(float);
    cudaFuncSetAttribute(CGFA_19533511262348_kernel,
                         cudaFuncAttributeMaxDynamicSharedMemorySize, smem_bytes);
    CGFA_19533511262348_kernel<<<NB, 256, smem_bytes>>>(
        A_src, emb_src, A_dst, emb_dst,
        Wa, ba, Wu, bu, Aff, Wc, bc, Wp1, Wp2, out);
}